// round 6
// baseline (speedup 1.0000x reference)
#include <cuda_runtime.h>
#include <math.h>

// ---------------- problem constants (fixed by reference) ----------------
#define T_TOK 4096
#define HID   2048
#define NH    16
#define NKV   4
#define DH    128
#define INTER 8192
#define BATCH 4
#define SEQ   1024
#define EPSV  1e-6f

// ---------------- scratch (static device globals; no runtime alloc) ----
__device__ float g_h   [T_TOK * HID];        // rmsnorm output (reused for h and h2)
__device__ float g_q   [T_TOK * NH  * DH];
__device__ float g_k   [T_TOK * NKV * DH];
__device__ float g_v   [T_TOK * NKV * DH];
__device__ float g_attn[T_TOK * NH  * DH];
__device__ float g_gate[T_TOK * INTER];
__device__ float g_up  [T_TOK * INTER];

// ======================================================================
// RMSNorm: one block (256 threads) per row of HID=2048
// ======================================================================
__global__ __launch_bounds__(256) void rmsnorm_kernel(
    const float* __restrict__ x, const float* __restrict__ w,
    float* __restrict__ out)
{
    int row = blockIdx.x;
    const float* xr = x + (long)row * HID;
    float*      outr = out + (long)row * HID;

    float s = 0.f;
    #pragma unroll
    for (int i = threadIdx.x; i < HID; i += 256) {
        float v = xr[i];
        s += v * v;
    }
    __shared__ float red[8];
    #pragma unroll
    for (int o = 16; o > 0; o >>= 1) s += __shfl_xor_sync(0xffffffff, s, o);
    if ((threadIdx.x & 31) == 0) red[threadIdx.x >> 5] = s;
    __syncthreads();
    if (threadIdx.x < 32) {
        float v = (threadIdx.x < 8) ? red[threadIdx.x] : 0.f;
        #pragma unroll
        for (int o = 4; o > 0; o >>= 1) v += __shfl_xor_sync(0xffffffff, v, o);
        if (threadIdx.x == 0) red[0] = v;
    }
    __syncthreads();
    float rinv = rsqrtf(red[0] / (float)HID + EPSV);

    #pragma unroll
    for (int i = threadIdx.x; i < HID; i += 256)
        outr[i] = xr[i] * rinv * w[i];
}

// ======================================================================
// SGEMM: C[M,N] = A[M,K] @ W[N,K]^T (+ bias[n]) (+ res[m,n])
// 128x128 block tile, BK=8, 256 threads, 8x8 per-thread register tile.
// All M,N,K here are multiples of 128/8 so no bounds checks.
// ======================================================================
__global__ __launch_bounds__(256) void sgemm_kernel(
    const float* __restrict__ A, const float* __restrict__ W,
    const float* __restrict__ bias, const float* __restrict__ res,
    float* __restrict__ C, int M, int N, int K)
{
    __shared__ float As[8][128];
    __shared__ float Bs[8][128];

    int tid = threadIdx.x;
    int bm = blockIdx.y, bn = blockIdx.x;

    int ar = tid >> 1;            // 0..127 : row within tile
    int ac = (tid & 1) * 4;       // 0 or 4 : k offset
    const float* Ag = A + (long)(bm * 128 + ar) * K + ac;
    const float* Wg = W + (long)(bn * 128 + ar) * K + ac;

    int ty = tid >> 4;            // 0..15
    int tx = tid & 15;            // 0..15

    float c[8][8] = {};
    float a[8], b[8];

    for (int k0 = 0; k0 < K; k0 += 8) {
        float4 av = *(const float4*)(Ag + k0);
        float4 bv = *(const float4*)(Wg + k0);
        As[ac + 0][ar] = av.x; As[ac + 1][ar] = av.y;
        As[ac + 2][ar] = av.z; As[ac + 3][ar] = av.w;
        Bs[ac + 0][ar] = bv.x; Bs[ac + 1][ar] = bv.y;
        Bs[ac + 2][ar] = bv.z; Bs[ac + 3][ar] = bv.w;
        __syncthreads();
        #pragma unroll
        for (int kk = 0; kk < 8; kk++) {
            #pragma unroll
            for (int i = 0; i < 8; i++) a[i] = As[kk][ty * 8 + i];
            #pragma unroll
            for (int j = 0; j < 8; j++) b[j] = Bs[kk][tx * 8 + j];
            #pragma unroll
            for (int i = 0; i < 8; i++)
                #pragma unroll
                for (int j = 0; j < 8; j++)
                    c[i][j] += a[i] * b[j];
        }
        __syncthreads();
    }

    #pragma unroll
    for (int i = 0; i < 8; i++) {
        long m = bm * 128 + ty * 8 + i;
        #pragma unroll
        for (int j = 0; j < 8; j++) {
            long n = bn * 128 + tx * 8 + j;
            float v = c[i][j];
            if (bias) v += bias[n];
            if (res)  v += res[m * N + n];
            C[m * N + n] = v;
        }
    }
}

// ======================================================================
// Per-head RMSNorm + RoPE, in-place on g_q / g_k.
// grid: (T_TOK, NH+NKV), 128 threads (one per d)
// ======================================================================
__global__ __launch_bounds__(128) void qknorm_rope_kernel(
    const float* __restrict__ cosb, const float* __restrict__ sinb,
    const float* __restrict__ qw, const float* __restrict__ kw)
{
    int t  = blockIdx.x;
    int hy = blockIdx.y;
    float* ptr; const float* w;
    if (hy < NH) { ptr = g_q + ((long)t * NH  + hy)        * DH; w = qw; }
    else         { ptr = g_k + ((long)t * NKV + (hy - NH)) * DH; w = kw; }

    int d = threadIdx.x;
    __shared__ float buf[DH];
    __shared__ float red[4];

    float v = ptr[d];
    buf[d] = v;
    float s = v * v;
    #pragma unroll
    for (int o = 16; o > 0; o >>= 1) s += __shfl_xor_sync(0xffffffff, s, o);
    if ((d & 31) == 0) red[d >> 5] = s;
    __syncthreads();
    float tot  = red[0] + red[1] + red[2] + red[3];
    float rinv = rsqrtf(tot / (float)DH + EPSV);

    int   p  = (d < 64) ? d + 64 : d - 64;
    float me = buf[d] * rinv * w[d];
    float pn = buf[p] * rinv * w[p];
    float rh = (d < 64) ? -pn : pn;
    float cv = cosb[(long)t * DH + d];
    float sv = sinb[(long)t * DH + d];
    ptr[d] = me * cv + rh * sv;
}

// ======================================================================
// Causal flash attention (fp32, online softmax, no S*S materialization).
// grid: (BATCH*NH, SEQ/64). block: 256 threads = 64 queries x 4 lanes.
// Each lane owns a 32-wide slice of d. K/V tiles of 32 keys in smem.
//
// DEADLOCK FIX vs previous round: the key loop bound is now warp-uniform
// (full KT iterations per tile); causality is applied per element by
// forcing sc = -inf for keys beyond qrow. The first iteration (kt=0,j=0)
// is always valid, so m is finite before any masked step -> corr/p well
// defined (p = exp(-inf - m) = 0 exactly).
// ======================================================================
#define QT 64
#define KT 32
__global__ __launch_bounds__(256) void attn_kernel()
{
    int bh = blockIdx.x;           // b*NH + h
    int qt = blockIdx.y;
    int b  = bh / NH, h = bh % NH;
    int kvh = h / (NH / NKV);      // h/4

    int tid   = threadIdx.x;
    int qi    = tid >> 2;          // 0..63
    int lane4 = tid & 3;           // 0..3
    int base  = lane4 * 32;

    int  qrow = qt * QT + qi;
    long t    = (long)b * SEQ + qrow;

    const float* qp = g_q + (t * NH + h) * DH + base;
    float qreg[32], oreg[32];
    #pragma unroll
    for (int i = 0; i < 32; i++) { qreg[i] = qp[i]; oreg[i] = 0.f; }

    float m = -INFINITY, l = 0.f;
    const float scale = 0.08838834764831845f;   // 1/sqrt(128)

    __shared__ float Ks[KT][DH];
    __shared__ float Vs[KT][DH];

    int nkt = (qt * QT + QT) / KT;   // key tiles covering the block's causal span
    for (int kt = 0; kt < nkt; kt++) {
        __syncthreads();
        // cooperative load of 32x128 K and V tiles (16 floats / thread each)
        for (int idx = tid; idx < KT * DH / 4; idx += 256) {
            int kr = (idx * 4) / DH;
            int kc = (idx * 4) % DH;
            long ktok = (long)b * SEQ + kt * KT + kr;
            *(float4*)&Ks[kr][kc] = *(const float4*)(g_k + (ktok * NKV + kvh) * DH + kc);
            *(float4*)&Vs[kr][kc] = *(const float4*)(g_v + (ktok * NKV + kvh) * DH + kc);
        }
        __syncthreads();

        #pragma unroll 4
        for (int j = 0; j < KT; j++) {          // UNIFORM bound: no divergent exit
            const float4* kr4 = (const float4*)&Ks[j][base];
            float d0 = 0.f, d1 = 0.f, d2 = 0.f, d3 = 0.f;
            #pragma unroll
            for (int i4 = 0; i4 < 8; i4++) {
                float4 kv = kr4[i4];
                d0 += qreg[i4 * 4 + 0] * kv.x;
                d1 += qreg[i4 * 4 + 1] * kv.y;
                d2 += qreg[i4 * 4 + 2] * kv.z;
                d3 += qreg[i4 * 4 + 3] * kv.w;
            }
            float dot = (d0 + d1) + (d2 + d3);
            dot += __shfl_xor_sync(0xffffffff, dot, 1);
            dot += __shfl_xor_sync(0xffffffff, dot, 2);

            // causal mask, per element (warp-uniform control flow)
            float sc = (kt * KT + j <= qrow) ? dot * scale : -INFINITY;

            float mn   = fmaxf(m, sc);
            float corr = __expf(m - mn);
            float p    = __expf(sc - mn);
            l = l * corr + p;
            m = mn;

            const float4* vr4 = (const float4*)&Vs[j][base];
            #pragma unroll
            for (int i4 = 0; i4 < 8; i4++) {
                float4 vv = vr4[i4];
                oreg[i4 * 4 + 0] = oreg[i4 * 4 + 0] * corr + p * vv.x;
                oreg[i4 * 4 + 1] = oreg[i4 * 4 + 1] * corr + p * vv.y;
                oreg[i4 * 4 + 2] = oreg[i4 * 4 + 2] * corr + p * vv.z;
                oreg[i4 * 4 + 3] = oreg[i4 * 4 + 3] * corr + p * vv.w;
            }
        }
    }

    float inv = 1.f / l;
    float* op = g_attn + (t * NH + h) * DH + base;
    #pragma unroll
    for (int i = 0; i < 32; i++) op[i] = oreg[i] * inv;
}

// ======================================================================
// act = silu(gate) * up, in place into g_gate. float4 per thread.
// ======================================================================
__global__ __launch_bounds__(256) void silu_mul_kernel()
{
    long i4 = ((long)blockIdx.x * 256 + threadIdx.x) * 4;
    float4 g = *(float4*)&g_gate[i4];
    float4 u = *(float4*)&g_up[i4];
    g.x = (g.x / (1.f + expf(-g.x))) * u.x;
    g.y = (g.y / (1.f + expf(-g.y))) * u.y;
    g.z = (g.z / (1.f + expf(-g.z))) * u.z;
    g.w = (g.w / (1.f + expf(-g.w))) * u.w;
    *(float4*)&g_gate[i4] = g;
}

// ======================================================================
// launch
// ======================================================================
extern "C" void kernel_launch(void* const* d_in, const int* in_sizes, int n_in,
                              void* d_out, int out_size)
{
    const float* x    = (const float*)d_in[0];
    // d_in[1] = attention_mask (causal tril, structure hardcoded)
    const float* cosb = (const float*)d_in[2];
    const float* sinb = (const float*)d_in[3];
    const float* wq   = (const float*)d_in[4];
    const float* bq   = (const float*)d_in[5];
    const float* wk   = (const float*)d_in[6];
    const float* bk   = (const float*)d_in[7];
    const float* wv   = (const float*)d_in[8];
    const float* bv   = (const float*)d_in[9];
    const float* wo   = (const float*)d_in[10];
    const float* qnw  = (const float*)d_in[11];
    const float* knw  = (const float*)d_in[12];
    const float* ln1  = (const float*)d_in[13];
    const float* ln2  = (const float*)d_in[14];
    const float* wg   = (const float*)d_in[15];
    const float* wu   = (const float*)d_in[16];
    const float* wd   = (const float*)d_in[17];
    float* out = (float*)d_out;

    float *ph, *pq, *pk, *pv, *pattn, *pgate, *pup;
    cudaGetSymbolAddress((void**)&ph,    g_h);
    cudaGetSymbolAddress((void**)&pq,    g_q);
    cudaGetSymbolAddress((void**)&pk,    g_k);
    cudaGetSymbolAddress((void**)&pv,    g_v);
    cudaGetSymbolAddress((void**)&pattn, g_attn);
    cudaGetSymbolAddress((void**)&pgate, g_gate);
    cudaGetSymbolAddress((void**)&pup,   g_up);

    // 1. h = rms(x, ln1)
    rmsnorm_kernel<<<T_TOK, 256>>>(x, ln1, ph);

    // 2-4. q/k/v projections
    sgemm_kernel<<<dim3((NH * DH) / 128, T_TOK / 128), 256>>>(
        ph, wq, bq, nullptr, pq, T_TOK, NH * DH, HID);
    sgemm_kernel<<<dim3((NKV * DH) / 128, T_TOK / 128), 256>>>(
        ph, wk, bk, nullptr, pk, T_TOK, NKV * DH, HID);
    sgemm_kernel<<<dim3((NKV * DH) / 128, T_TOK / 128), 256>>>(
        ph, wv, bv, nullptr, pv, T_TOK, NKV * DH, HID);

    // 5. per-head rmsnorm + rope (in place)
    qknorm_rope_kernel<<<dim3(T_TOK, NH + NKV), 128>>>(cosb, sinb, qnw, knw);

    // 6. causal attention -> g_attn
    attn_kernel<<<dim3(BATCH * NH, SEQ / QT), 256>>>();

    // 7. x1 = x + attn @ wo^T   (into d_out)
    sgemm_kernel<<<dim3(HID / 128, T_TOK / 128), 256>>>(
        pattn, wo, nullptr, x, out, T_TOK, HID, NH * DH);

    // 8. h2 = rms(x1, ln2)
    rmsnorm_kernel<<<T_TOK, 256>>>(out, ln2, ph);

    // 9-10. gate / up projections
    sgemm_kernel<<<dim3(INTER / 128, T_TOK / 128), 256>>>(
        ph, wg, nullptr, nullptr, pgate, T_TOK, INTER, HID);
    sgemm_kernel<<<dim3(INTER / 128, T_TOK / 128), 256>>>(
        ph, wu, nullptr, nullptr, pup, T_TOK, INTER, HID);

    // 11. act = silu(gate) * up  (in place into g_gate)
    silu_mul_kernel<<<(T_TOK * (long)INTER) / (256 * 4), 256>>>();

    // 12. out = x1 + act @ wd^T   (residual read of d_out, write d_out)
    sgemm_kernel<<<dim3(HID / 128, T_TOK / 128), 256>>>(
        pgate, wd, nullptr, out, out, T_TOK, HID, INTER);
}

// round 10
// speedup vs baseline: 2.1136x; 2.1136x over previous
#include <cuda_runtime.h>
#include <cuda_bf16.h>
#include <math.h>
#include <stdint.h>

// ---------------- problem constants ----------------
#define T_TOK 4096
#define HID   2048
#define NH    16
#define NKV   4
#define DH    128
#define INTER 8192
#define BATCH 4
#define SEQ   1024
#define EPSV  1e-6f

// ---------------- scratch (static device globals; no runtime alloc) ----
__device__ __align__(256) float g_q   [T_TOK * NH  * DH];
__device__ __align__(256) float g_k   [T_TOK * NKV * DH];
__device__ __align__(256) float g_v   [T_TOK * NKV * DH];
__device__ __align__(256) float g_gate[T_TOK * INTER];
__device__ __align__(256) float g_up  [T_TOK * INTER];
// bf16 hi/lo activation operands
__device__ __align__(256) __nv_bfloat16 g_h_hi   [T_TOK * HID];
__device__ __align__(256) __nv_bfloat16 g_h_lo   [T_TOK * HID];
__device__ __align__(256) __nv_bfloat16 g_attn_hi[T_TOK * NH * DH];
__device__ __align__(256) __nv_bfloat16 g_attn_lo[T_TOK * NH * DH];
__device__ __align__(256) __nv_bfloat16 g_act_hi [T_TOK * INTER];
__device__ __align__(256) __nv_bfloat16 g_act_lo [T_TOK * INTER];
// bf16 hi/lo weights
__device__ __align__(256) __nv_bfloat16 w_q_hi[NH  * DH * HID];
__device__ __align__(256) __nv_bfloat16 w_q_lo[NH  * DH * HID];
__device__ __align__(256) __nv_bfloat16 w_k_hi[NKV * DH * HID];
__device__ __align__(256) __nv_bfloat16 w_k_lo[NKV * DH * HID];
__device__ __align__(256) __nv_bfloat16 w_v_hi[NKV * DH * HID];
__device__ __align__(256) __nv_bfloat16 w_v_lo[NKV * DH * HID];
__device__ __align__(256) __nv_bfloat16 w_o_hi[HID * NH * DH];
__device__ __align__(256) __nv_bfloat16 w_o_lo[HID * NH * DH];
__device__ __align__(256) __nv_bfloat16 w_g_hi[INTER * HID];
__device__ __align__(256) __nv_bfloat16 w_g_lo[INTER * HID];
__device__ __align__(256) __nv_bfloat16 w_u_hi[INTER * HID];
__device__ __align__(256) __nv_bfloat16 w_u_lo[INTER * HID];
__device__ __align__(256) __nv_bfloat16 w_d_hi[HID * INTER];
__device__ __align__(256) __nv_bfloat16 w_d_lo[HID * INTER];

// ---------------- PTX helpers (all arch-agnostic: sm_80+ ops only) ----
__device__ __forceinline__ uint32_t smem_u32(const void* p) {
    uint32_t a;
    asm("{ .reg .u64 t; cvta.to.shared.u64 t, %1; cvt.u32.u64 %0, t; }" : "=r"(a) : "l"(p));
    return a;
}
__device__ __forceinline__ void ldm_x4(uint32_t* r, uint32_t addr) {
    asm volatile("ldmatrix.sync.aligned.m8n8.x4.shared.b16 {%0,%1,%2,%3}, [%4];"
        : "=r"(r[0]), "=r"(r[1]), "=r"(r[2]), "=r"(r[3]) : "r"(addr));
}
__device__ __forceinline__ void ldm_x2(uint32_t* r, uint32_t addr) {
    asm volatile("ldmatrix.sync.aligned.m8n8.x2.shared.b16 {%0,%1}, [%2];"
        : "=r"(r[0]), "=r"(r[1]) : "r"(addr));
}
__device__ __forceinline__ void mma_bf16(float* c, const uint32_t* a, const uint32_t* b) {
    asm volatile("mma.sync.aligned.m16n8k16.row.col.f32.bf16.bf16.f32 "
        "{%0,%1,%2,%3}, {%4,%5,%6,%7}, {%8,%9}, {%0,%1,%2,%3};"
        : "+f"(c[0]), "+f"(c[1]), "+f"(c[2]), "+f"(c[3])
        : "r"(a[0]), "r"(a[1]), "r"(a[2]), "r"(a[3]), "r"(b[0]), "r"(b[1]));
}
__device__ __forceinline__ void cp16(uint32_t saddr, const void* g) {
    asm volatile("cp.async.cg.shared.global [%0], [%1], 16;" :: "r"(saddr), "l"(g));
}
#define CP_COMMIT() asm volatile("cp.async.commit_group;" ::: "memory")
#define CP_WAIT0()  asm volatile("cp.async.wait_group 0;" ::: "memory")

// hi/lo split store of 4 consecutive fp32
__device__ __forceinline__ void store_hilo4(float4 v, __nv_bfloat16* hi, __nv_bfloat16* lo, long idx) {
    __nv_bfloat16 h[4], l[4];
    float f[4] = {v.x, v.y, v.z, v.w};
    #pragma unroll
    for (int i = 0; i < 4; i++) {
        h[i] = __float2bfloat16(f[i]);
        l[i] = __float2bfloat16(f[i] - __bfloat162float(h[i]));
    }
    *(uint2*)(hi + idx) = *(const uint2*)h;
    *(uint2*)(lo + idx) = *(const uint2*)l;
}

// ======================================================================
// weight fp32 -> bf16 hi/lo conversion
// ======================================================================
__global__ __launch_bounds__(256) void convert_hilo_kernel(
    const float* __restrict__ src, __nv_bfloat16* __restrict__ hi,
    __nv_bfloat16* __restrict__ lo, int n4)
{
    long i = (long)blockIdx.x * 256 + threadIdx.x;
    if (i < n4) store_hilo4(((const float4*)src)[i], hi, lo, i * 4);
}

// ======================================================================
// RMSNorm: fp32 in -> bf16 hi/lo out. One block per row of HID=2048.
// ======================================================================
__global__ __launch_bounds__(256) void rmsnorm_kernel(
    const float* __restrict__ x, const float* __restrict__ w,
    __nv_bfloat16* __restrict__ ohi, __nv_bfloat16* __restrict__ olo)
{
    int row = blockIdx.x;
    const float4* xr = (const float4*)(x + (long)row * HID);
    const float4* wr = (const float4*)w;

    float4 v0 = xr[threadIdx.x];
    float4 v1 = xr[threadIdx.x + 256];
    float s = v0.x*v0.x + v0.y*v0.y + v0.z*v0.z + v0.w*v0.w
            + v1.x*v1.x + v1.y*v1.y + v1.z*v1.z + v1.w*v1.w;

    __shared__ float red[8];
    #pragma unroll
    for (int o = 16; o > 0; o >>= 1) s += __shfl_xor_sync(0xffffffff, s, o);
    if ((threadIdx.x & 31) == 0) red[threadIdx.x >> 5] = s;
    __syncthreads();
    if (threadIdx.x < 32) {
        float t = (threadIdx.x < 8) ? red[threadIdx.x] : 0.f;
        #pragma unroll
        for (int o = 4; o > 0; o >>= 1) t += __shfl_xor_sync(0xffffffff, t, o);
        if (threadIdx.x == 0) red[0] = t;
    }
    __syncthreads();
    float rinv = rsqrtf(red[0] / (float)HID + EPSV);

    long base = (long)row * HID;
    float4 w0 = wr[threadIdx.x], w1 = wr[threadIdx.x + 256];
    float4 y0 = make_float4(v0.x*rinv*w0.x, v0.y*rinv*w0.y, v0.z*rinv*w0.z, v0.w*rinv*w0.w);
    float4 y1 = make_float4(v1.x*rinv*w1.x, v1.y*rinv*w1.y, v1.z*rinv*w1.z, v1.w*rinv*w1.w);
    store_hilo4(y0, ohi, olo, base + threadIdx.x * 4);
    store_hilo4(y1, ohi, olo, base + (threadIdx.x + 256) * 4);
}

// ======================================================================
// bf16 split GEMM on mma.sync (m16n8k16): C = A@W^T (+bias)(+res), fp32.
// 128x128 block tile, BK=64, 2-stage cp.async pipeline, SW128 smem.
// 8 warps in 2(M)x4(N); warp tile 64x32 = 4x4 m16n8 atoms.
// 3 split products (AhiWhi + AhiWlo + AloWhi) share fp32 accumulators.
// ======================================================================
#define GSTAGE 65536                      // 4 tiles x 16KB (128x64 bf16 SW128)
#define GSMEM  (2 * GSTAGE)

__global__ __launch_bounds__(256, 1) void hgemm_kernel(
    const __nv_bfloat16* __restrict__ Ahi, const __nv_bfloat16* __restrict__ Alo,
    const __nv_bfloat16* __restrict__ Whi, const __nv_bfloat16* __restrict__ Wlo,
    const float* __restrict__ bias, const float* __restrict__ res,
    float* __restrict__ C, int M, int N, int K)
{
    extern __shared__ char smem[];
    uint32_t sb = smem_u32(smem);
    int tid = threadIdx.x, wid = tid >> 5, lt = tid & 31;
    int bm = blockIdx.y, bn = blockIdx.x;
    int wm = wid & 1, wn = wid >> 1;

    long aoff = (long)bm * 128 * K;
    long boff = (long)bn * 128 * K;
    const __nv_bfloat16* srcs[4] = {Ahi + aoff, Alo + aoff, Whi + boff, Wlo + boff};

    // ---- global->smem fill coords (cp.async, 16B per chunk) ----
    int r0   = tid >> 3;                  // base row, +32 per j
    int cb0  = (tid & 7) * 16;            // byte col in 128B row
    int gcol = (tid & 7) * 8;             // element col
    uint32_t sw_st = (uint32_t)(r0 & 7) << 4;
    uint32_t st_off[4];
    #pragma unroll
    for (int j = 0; j < 4; j++)
        st_off[j] = (uint32_t)(r0 + j * 32) * 128 + ((uint32_t)cb0 ^ sw_st);

    // ---- ldmatrix address precompute ----
    int rA = wm * 64 + (lt & 15);
    uint32_t swA   = (uint32_t)(rA & 7) << 4;
    uint32_t baseA = (uint32_t)rA * 128;
    uint32_t cbA   = (uint32_t)((lt >> 4) << 4);       // 0 / 16

    int nB = wn * 32 + (lt & 7);
    uint32_t swB   = (uint32_t)(nB & 7) << 4;
    uint32_t baseB = (uint32_t)nB * 128;
    uint32_t cbB   = (uint32_t)(((lt >> 3) & 1) << 4); // 0 / 16

    float acc[4][4][4];
    #pragma unroll
    for (int mi = 0; mi < 4; mi++)
        #pragma unroll
        for (int ni = 0; ni < 4; ni++)
            #pragma unroll
            for (int q = 0; q < 4; q++) acc[mi][ni][q] = 0.f;

    int nit = K / 64;

    // prologue: stage 0
    {
        uint32_t sp = sb;
        #pragma unroll
        for (int tl = 0; tl < 4; tl++)
            #pragma unroll
            for (int j = 0; j < 4; j++)
                cp16(sp + tl * 16384 + st_off[j],
                     srcs[tl] + (long)(r0 + j * 32) * K + gcol);
        CP_COMMIT();
    }

    for (int it = 0; it < nit; it++) {
        int p = it & 1;
        CP_WAIT0();
        __syncthreads();

        if (it + 1 < nit) {
            int k0 = (it + 1) * 64;
            uint32_t sp = sb + (p ^ 1) * GSTAGE;
            #pragma unroll
            for (int tl = 0; tl < 4; tl++)
                #pragma unroll
                for (int j = 0; j < 4; j++)
                    cp16(sp + tl * 16384 + st_off[j],
                         srcs[tl] + (long)(r0 + j * 32) * K + k0 + gcol);
            CP_COMMIT();
        }

        uint32_t tAhi = sb + p * GSTAGE;
        uint32_t tAlo = tAhi + 16384;
        uint32_t tWhi = tAhi + 32768;
        uint32_t tWlo = tAhi + 49152;

        #pragma unroll
        for (int ks = 0; ks < 4; ks++) {
            uint32_t ca  = ((uint32_t)(ks * 32) + cbA) ^ swA;
            uint32_t cbv = ((uint32_t)(ks * 32) + cbB) ^ swB;
            uint32_t a[4][4], bh[4][2], bl[4][2];

            #pragma unroll
            for (int mi = 0; mi < 4; mi++)
                ldm_x4(a[mi], tAhi + baseA + mi * 2048 + ca);
            #pragma unroll
            for (int ni = 0; ni < 4; ni++)
                ldm_x2(bh[ni], tWhi + baseB + ni * 1024 + cbv);
            #pragma unroll
            for (int mi = 0; mi < 4; mi++)
                #pragma unroll
                for (int ni = 0; ni < 4; ni++)
                    mma_bf16(acc[mi][ni], a[mi], bh[ni]);

            #pragma unroll
            for (int ni = 0; ni < 4; ni++)
                ldm_x2(bl[ni], tWlo + baseB + ni * 1024 + cbv);
            #pragma unroll
            for (int mi = 0; mi < 4; mi++)
                #pragma unroll
                for (int ni = 0; ni < 4; ni++)
                    mma_bf16(acc[mi][ni], a[mi], bl[ni]);

            #pragma unroll
            for (int mi = 0; mi < 4; mi++)
                ldm_x4(a[mi], tAlo + baseA + mi * 2048 + ca);
            #pragma unroll
            for (int mi = 0; mi < 4; mi++)
                #pragma unroll
                for (int ni = 0; ni < 4; ni++)
                    mma_bf16(acc[mi][ni], a[mi], bh[ni]);
        }
    }

    // ---- epilogue ----
    int row0 = bm * 128 + wm * 64 + (lt >> 2);
    int col0 = bn * 128 + wn * 32 + (lt & 3) * 2;
    #pragma unroll
    for (int mi = 0; mi < 4; mi++) {
        #pragma unroll
        for (int ni = 0; ni < 4; ni++) {
            long r = row0 + mi * 16;
            long c = col0 + ni * 8;
            float v0 = acc[mi][ni][0], v1 = acc[mi][ni][1];
            float v2 = acc[mi][ni][2], v3 = acc[mi][ni][3];
            if (bias) {
                float b0 = bias[c], b1 = bias[c + 1];
                v0 += b0; v1 += b1; v2 += b0; v3 += b1;
            }
            if (res) {
                const float2 r01 = *(const float2*)(res + r * N + c);
                const float2 r23 = *(const float2*)(res + (r + 8) * N + c);
                v0 += r01.x; v1 += r01.y; v2 += r23.x; v3 += r23.y;
            }
            *(float2*)(C + r * N + c)       = make_float2(v0, v1);
            *(float2*)(C + (r + 8) * N + c) = make_float2(v2, v3);
        }
    }
}

// ======================================================================
// Per-head RMSNorm + RoPE, in-place on g_q / g_k.
// ======================================================================
__global__ __launch_bounds__(128) void qknorm_rope_kernel(
    const float* __restrict__ cosb, const float* __restrict__ sinb,
    const float* __restrict__ qw, const float* __restrict__ kw)
{
    int t  = blockIdx.x;
    int hy = blockIdx.y;
    float* ptr; const float* w;
    if (hy < NH) { ptr = g_q + ((long)t * NH  + hy)        * DH; w = qw; }
    else         { ptr = g_k + ((long)t * NKV + (hy - NH)) * DH; w = kw; }

    int d = threadIdx.x;
    __shared__ float buf[DH];
    __shared__ float red[4];

    float v = ptr[d];
    buf[d] = v;
    float s = v * v;
    #pragma unroll
    for (int o = 16; o > 0; o >>= 1) s += __shfl_xor_sync(0xffffffff, s, o);
    if ((d & 31) == 0) red[d >> 5] = s;
    __syncthreads();
    float tot  = red[0] + red[1] + red[2] + red[3];
    float rinv = rsqrtf(tot / (float)DH + EPSV);

    int   p  = (d < 64) ? d + 64 : d - 64;
    float me = buf[d] * rinv * w[d];
    float pn = buf[p] * rinv * w[p];
    float rh = (d < 64) ? -pn : pn;
    float cv = cosb[(long)t * DH + d];
    float sv = sinb[(long)t * DH + d];
    ptr[d] = me * cv + rh * sv;
}

// ======================================================================
// Causal flash attention (fp32 online softmax). Output -> bf16 hi/lo.
// Warp-uniform inner loop; causality enforced per element via -inf.
// ======================================================================
#define QT 64
#define KT 32
__global__ __launch_bounds__(256) void attn_kernel()
{
    int bh = blockIdx.x;
    int qt = blockIdx.y;
    int b  = bh / NH, h = bh % NH;
    int kvh = h / (NH / NKV);

    int tid   = threadIdx.x;
    int qi    = tid >> 2;
    int lane4 = tid & 3;
    int base  = lane4 * 32;

    int  qrow = qt * QT + qi;
    long t    = (long)b * SEQ + qrow;

    const float* qp = g_q + (t * NH + h) * DH + base;
    float qreg[32], oreg[32];
    #pragma unroll
    for (int i = 0; i < 32; i++) { qreg[i] = qp[i]; oreg[i] = 0.f; }

    float m = -INFINITY, l = 0.f;
    const float scale = 0.08838834764831845f;

    __shared__ float Ks[KT][DH];
    __shared__ float Vs[KT][DH];

    int nkt = (qt * QT + QT) / KT;
    for (int kt = 0; kt < nkt; kt++) {
        __syncthreads();
        for (int idx = tid; idx < KT * DH / 4; idx += 256) {
            int kr = (idx * 4) / DH;
            int kc = (idx * 4) % DH;
            long ktok = (long)b * SEQ + kt * KT + kr;
            *(float4*)&Ks[kr][kc] = *(const float4*)(g_k + (ktok * NKV + kvh) * DH + kc);
            *(float4*)&Vs[kr][kc] = *(const float4*)(g_v + (ktok * NKV + kvh) * DH + kc);
        }
        __syncthreads();

        #pragma unroll 4
        for (int j = 0; j < KT; j++) {
            const float4* kr4 = (const float4*)&Ks[j][base];
            float d0 = 0.f, d1 = 0.f, d2 = 0.f, d3 = 0.f;
            #pragma unroll
            for (int i4 = 0; i4 < 8; i4++) {
                float4 kv = kr4[i4];
                d0 += qreg[i4 * 4 + 0] * kv.x;
                d1 += qreg[i4 * 4 + 1] * kv.y;
                d2 += qreg[i4 * 4 + 2] * kv.z;
                d3 += qreg[i4 * 4 + 3] * kv.w;
            }
            float dot = (d0 + d1) + (d2 + d3);
            dot += __shfl_xor_sync(0xffffffff, dot, 1);
            dot += __shfl_xor_sync(0xffffffff, dot, 2);

            float sc = (kt * KT + j <= qrow) ? dot * scale : -INFINITY;

            float mn   = fmaxf(m, sc);
            float corr = __expf(m - mn);
            float p    = __expf(sc - mn);
            l = l * corr + p;
            m = mn;

            const float4* vr4 = (const float4*)&Vs[j][base];
            #pragma unroll
            for (int i4 = 0; i4 < 8; i4++) {
                float4 vv = vr4[i4];
                oreg[i4 * 4 + 0] = oreg[i4 * 4 + 0] * corr + p * vv.x;
                oreg[i4 * 4 + 1] = oreg[i4 * 4 + 1] * corr + p * vv.y;
                oreg[i4 * 4 + 2] = oreg[i4 * 4 + 2] * corr + p * vv.z;
                oreg[i4 * 4 + 3] = oreg[i4 * 4 + 3] * corr + p * vv.w;
            }
        }
    }

    float inv = 1.f / l;
    long obase = (t * NH + h) * DH + base;
    #pragma unroll
    for (int q = 0; q < 8; q++) {
        float4 v = make_float4(oreg[q*4+0]*inv, oreg[q*4+1]*inv,
                               oreg[q*4+2]*inv, oreg[q*4+3]*inv);
        store_hilo4(v, g_attn_hi, g_attn_lo, obase + q * 4);
    }
}

// ======================================================================
// act = silu(gate) * up -> bf16 hi/lo
// ======================================================================
__global__ __launch_bounds__(256) void silu_mul_kernel()
{
    long i4 = ((long)blockIdx.x * 256 + threadIdx.x) * 4;
    float4 g = *(float4*)&g_gate[i4];
    float4 u = *(float4*)&g_up[i4];
    g.x = (g.x / (1.f + __expf(-g.x))) * u.x;
    g.y = (g.y / (1.f + __expf(-g.y))) * u.y;
    g.z = (g.z / (1.f + __expf(-g.z))) * u.z;
    g.w = (g.w / (1.f + __expf(-g.w))) * u.w;
    store_hilo4(g, g_act_hi, g_act_lo, i4);
}

// ======================================================================
// launch
// ======================================================================
extern "C" void kernel_launch(void* const* d_in, const int* in_sizes, int n_in,
                              void* d_out, int out_size)
{
    const float* x    = (const float*)d_in[0];
    const float* cosb = (const float*)d_in[2];
    const float* sinb = (const float*)d_in[3];
    const float* wq   = (const float*)d_in[4];
    const float* bq   = (const float*)d_in[5];
    const float* wk   = (const float*)d_in[6];
    const float* bk   = (const float*)d_in[7];
    const float* wv   = (const float*)d_in[8];
    const float* bv   = (const float*)d_in[9];
    const float* wo   = (const float*)d_in[10];
    const float* qnw  = (const float*)d_in[11];
    const float* knw  = (const float*)d_in[12];
    const float* ln1  = (const float*)d_in[13];
    const float* ln2  = (const float*)d_in[14];
    const float* wg   = (const float*)d_in[15];
    const float* wu   = (const float*)d_in[16];
    const float* wd   = (const float*)d_in[17];
    float* out = (float*)d_out;

    float *pq, *pk, *pv, *pgate, *pup;
    __nv_bfloat16 *phh, *phl, *pah, *pal, *pch, *pcl;
    __nv_bfloat16 *qh, *ql, *kh, *kl, *vh, *vl, *oh, *ol, *gh, *gl, *uh, *ul, *dh, *dl;
    cudaGetSymbolAddress((void**)&pq,    g_q);
    cudaGetSymbolAddress((void**)&pk,    g_k);
    cudaGetSymbolAddress((void**)&pv,    g_v);
    cudaGetSymbolAddress((void**)&pgate, g_gate);
    cudaGetSymbolAddress((void**)&pup,   g_up);
    cudaGetSymbolAddress((void**)&phh, g_h_hi);   cudaGetSymbolAddress((void**)&phl, g_h_lo);
    cudaGetSymbolAddress((void**)&pah, g_attn_hi);cudaGetSymbolAddress((void**)&pal, g_attn_lo);
    cudaGetSymbolAddress((void**)&pch, g_act_hi); cudaGetSymbolAddress((void**)&pcl, g_act_lo);
    cudaGetSymbolAddress((void**)&qh, w_q_hi);    cudaGetSymbolAddress((void**)&ql, w_q_lo);
    cudaGetSymbolAddress((void**)&kh, w_k_hi);    cudaGetSymbolAddress((void**)&kl, w_k_lo);
    cudaGetSymbolAddress((void**)&vh, w_v_hi);    cudaGetSymbolAddress((void**)&vl, w_v_lo);
    cudaGetSymbolAddress((void**)&oh, w_o_hi);    cudaGetSymbolAddress((void**)&ol, w_o_lo);
    cudaGetSymbolAddress((void**)&gh, w_g_hi);    cudaGetSymbolAddress((void**)&gl, w_g_lo);
    cudaGetSymbolAddress((void**)&uh, w_u_hi);    cudaGetSymbolAddress((void**)&ul, w_u_lo);
    cudaGetSymbolAddress((void**)&dh, w_d_hi);    cudaGetSymbolAddress((void**)&dl, w_d_lo);

    // not a stream op; safe under capture, deterministic every call
    cudaFuncSetAttribute(hgemm_kernel, cudaFuncAttributeMaxDynamicSharedMemorySize, GSMEM);

    // weight fp32 -> bf16 hi/lo
    auto conv = [&](const float* s, __nv_bfloat16* h, __nv_bfloat16* l, long n) {
        convert_hilo_kernel<<<(unsigned)((n / 4 + 255) / 256), 256>>>(s, h, l, (int)(n / 4));
    };
    conv(wq, qh, ql, (long)NH  * DH * HID);
    conv(wk, kh, kl, (long)NKV * DH * HID);
    conv(wv, vh, vl, (long)NKV * DH * HID);
    conv(wo, oh, ol, (long)HID * NH * DH);
    conv(wg, gh, gl, (long)INTER * HID);
    conv(wu, uh, ul, (long)INTER * HID);
    conv(wd, dh, dl, (long)HID * INTER);

    // 1. h = rms(x, ln1) -> bf16 hi/lo
    rmsnorm_kernel<<<T_TOK, 256>>>(x, ln1, phh, phl);

    // 2-4. q/k/v projections (tensor cores via mma.sync)
    hgemm_kernel<<<dim3((NH * DH) / 128, T_TOK / 128), 256, GSMEM>>>(
        phh, phl, qh, ql, bq, nullptr, pq, T_TOK, NH * DH, HID);
    hgemm_kernel<<<dim3((NKV * DH) / 128, T_TOK / 128), 256, GSMEM>>>(
        phh, phl, kh, kl, bk, nullptr, pk, T_TOK, NKV * DH, HID);
    hgemm_kernel<<<dim3((NKV * DH) / 128, T_TOK / 128), 256, GSMEM>>>(
        phh, phl, vh, vl, bv, nullptr, pv, T_TOK, NKV * DH, HID);

    // 5. per-head rmsnorm + rope
    qknorm_rope_kernel<<<dim3(T_TOK, NH + NKV), 128>>>(cosb, sinb, qnw, knw);

    // 6. attention -> bf16 hi/lo
    attn_kernel<<<dim3(BATCH * NH, SEQ / QT), 256>>>();

    // 7. x1 = x + attn @ wo^T  (into d_out)
    hgemm_kernel<<<dim3(HID / 128, T_TOK / 128), 256, GSMEM>>>(
        pah, pal, oh, ol, nullptr, x, out, T_TOK, HID, NH * DH);

    // 8. h2 = rms(x1, ln2) -> bf16 hi/lo
    rmsnorm_kernel<<<T_TOK, 256>>>(out, ln2, phh, phl);

    // 9-10. gate / up projections
    hgemm_kernel<<<dim3(INTER / 128, T_TOK / 128), 256, GSMEM>>>(
        phh, phl, gh, gl, nullptr, nullptr, pgate, T_TOK, INTER, HID);
    hgemm_kernel<<<dim3(INTER / 128, T_TOK / 128), 256, GSMEM>>>(
        phh, phl, uh, ul, nullptr, nullptr, pup, T_TOK, INTER, HID);

    // 11. act = silu(gate) * up -> bf16 hi/lo
    silu_mul_kernel<<<(T_TOK * (long)INTER) / (256 * 4), 256>>>();

    // 12. out = x1 + act @ wd^T
    hgemm_kernel<<<dim3(HID / 128, T_TOK / 128), 256, GSMEM>>>(
        pch, pcl, dh, dl, nullptr, out, out, T_TOK, HID, INTER);
}

// round 11
// speedup vs baseline: 2.2582x; 1.0684x over previous
#include <cuda_runtime.h>
#include <cuda_bf16.h>
#include <math.h>
#include <stdint.h>

// ---------------- problem constants ----------------
#define T_TOK 4096
#define HID   2048
#define NH    16
#define NKV   4
#define DH    128
#define INTER 8192
#define BATCH 4
#define SEQ   1024
#define EPSV  1e-6f

// ---------------- scratch (static device globals; no runtime alloc) ----
__device__ __align__(256) float g_q   [T_TOK * NH  * DH];
__device__ __align__(256) float g_k   [T_TOK * NKV * DH];
__device__ __align__(256) float g_v   [T_TOK * NKV * DH];
__device__ __align__(256) float g_gate[T_TOK * INTER];
__device__ __align__(256) float g_up  [T_TOK * INTER];
// bf16 hi/lo activation operands
__device__ __align__(256) __nv_bfloat16 g_h_hi   [T_TOK * HID];
__device__ __align__(256) __nv_bfloat16 g_h_lo   [T_TOK * HID];
__device__ __align__(256) __nv_bfloat16 g_attn_hi[T_TOK * NH * DH];
__device__ __align__(256) __nv_bfloat16 g_attn_lo[T_TOK * NH * DH];
__device__ __align__(256) __nv_bfloat16 g_act_hi [T_TOK * INTER];
__device__ __align__(256) __nv_bfloat16 g_act_lo [T_TOK * INTER];
// bf16 hi/lo weights
__device__ __align__(256) __nv_bfloat16 w_q_hi[NH  * DH * HID];
__device__ __align__(256) __nv_bfloat16 w_q_lo[NH  * DH * HID];
__device__ __align__(256) __nv_bfloat16 w_k_hi[NKV * DH * HID];
__device__ __align__(256) __nv_bfloat16 w_k_lo[NKV * DH * HID];
__device__ __align__(256) __nv_bfloat16 w_v_hi[NKV * DH * HID];
__device__ __align__(256) __nv_bfloat16 w_v_lo[NKV * DH * HID];
__device__ __align__(256) __nv_bfloat16 w_o_hi[HID * NH * DH];
__device__ __align__(256) __nv_bfloat16 w_o_lo[HID * NH * DH];
__device__ __align__(256) __nv_bfloat16 w_g_hi[INTER * HID];
__device__ __align__(256) __nv_bfloat16 w_g_lo[INTER * HID];
__device__ __align__(256) __nv_bfloat16 w_u_hi[INTER * HID];
__device__ __align__(256) __nv_bfloat16 w_u_lo[INTER * HID];
__device__ __align__(256) __nv_bfloat16 w_d_hi[HID * INTER];
__device__ __align__(256) __nv_bfloat16 w_d_lo[HID * INTER];

// ---------------- PTX helpers (all arch-agnostic: sm_80+ ops only) ----
__device__ __forceinline__ uint32_t smem_u32(const void* p) {
    uint32_t a;
    asm("{ .reg .u64 t; cvta.to.shared.u64 t, %1; cvt.u32.u64 %0, t; }" : "=r"(a) : "l"(p));
    return a;
}
__device__ __forceinline__ void ldm_x4(uint32_t* r, uint32_t addr) {
    asm volatile("ldmatrix.sync.aligned.m8n8.x4.shared.b16 {%0,%1,%2,%3}, [%4];"
        : "=r"(r[0]), "=r"(r[1]), "=r"(r[2]), "=r"(r[3]) : "r"(addr));
}
__device__ __forceinline__ void ldm_x2(uint32_t* r, uint32_t addr) {
    asm volatile("ldmatrix.sync.aligned.m8n8.x2.shared.b16 {%0,%1}, [%2];"
        : "=r"(r[0]), "=r"(r[1]) : "r"(addr));
}
__device__ __forceinline__ void mma_bf16(float* c, const uint32_t* a, const uint32_t* b) {
    asm volatile("mma.sync.aligned.m16n8k16.row.col.f32.bf16.bf16.f32 "
        "{%0,%1,%2,%3}, {%4,%5,%6,%7}, {%8,%9}, {%0,%1,%2,%3};"
        : "+f"(c[0]), "+f"(c[1]), "+f"(c[2]), "+f"(c[3])
        : "r"(a[0]), "r"(a[1]), "r"(a[2]), "r"(a[3]), "r"(b[0]), "r"(b[1]));
}
__device__ __forceinline__ void cp16(uint32_t saddr, const void* g) {
    asm volatile("cp.async.cg.shared.global [%0], [%1], 16;" :: "r"(saddr), "l"(g));
}
#define CP_COMMIT() asm volatile("cp.async.commit_group;" ::: "memory")
#define CP_WAIT0()  asm volatile("cp.async.wait_group 0;" ::: "memory")

// hi/lo split store of 4 consecutive fp32
__device__ __forceinline__ void store_hilo4(float4 v, __nv_bfloat16* hi, __nv_bfloat16* lo, long idx) {
    __nv_bfloat16 h[4], l[4];
    float f[4] = {v.x, v.y, v.z, v.w};
    #pragma unroll
    for (int i = 0; i < 4; i++) {
        h[i] = __float2bfloat16(f[i]);
        l[i] = __float2bfloat16(f[i] - __bfloat162float(h[i]));
    }
    *(uint2*)(hi + idx) = *(const uint2*)h;
    *(uint2*)(lo + idx) = *(const uint2*)l;
}

// ======================================================================
// weight fp32 -> bf16 hi/lo conversion
// ======================================================================
__global__ __launch_bounds__(256) void convert_hilo_kernel(
    const float* __restrict__ src, __nv_bfloat16* __restrict__ hi,
    __nv_bfloat16* __restrict__ lo, int n4)
{
    long i = (long)blockIdx.x * 256 + threadIdx.x;
    if (i < n4) store_hilo4(((const float4*)src)[i], hi, lo, i * 4);
}

// ======================================================================
// RMSNorm: fp32 in -> bf16 hi/lo out. One block per row of HID=2048.
// ======================================================================
__global__ __launch_bounds__(256) void rmsnorm_kernel(
    const float* __restrict__ x, const float* __restrict__ w,
    __nv_bfloat16* __restrict__ ohi, __nv_bfloat16* __restrict__ olo)
{
    int row = blockIdx.x;
    const float4* xr = (const float4*)(x + (long)row * HID);
    const float4* wr = (const float4*)w;

    float4 v0 = xr[threadIdx.x];
    float4 v1 = xr[threadIdx.x + 256];
    float s = v0.x*v0.x + v0.y*v0.y + v0.z*v0.z + v0.w*v0.w
            + v1.x*v1.x + v1.y*v1.y + v1.z*v1.z + v1.w*v1.w;

    __shared__ float red[8];
    #pragma unroll
    for (int o = 16; o > 0; o >>= 1) s += __shfl_xor_sync(0xffffffff, s, o);
    if ((threadIdx.x & 31) == 0) red[threadIdx.x >> 5] = s;
    __syncthreads();
    if (threadIdx.x < 32) {
        float t = (threadIdx.x < 8) ? red[threadIdx.x] : 0.f;
        #pragma unroll
        for (int o = 4; o > 0; o >>= 1) t += __shfl_xor_sync(0xffffffff, t, o);
        if (threadIdx.x == 0) red[0] = t;
    }
    __syncthreads();
    float rinv = rsqrtf(red[0] / (float)HID + EPSV);

    long base = (long)row * HID;
    float4 w0 = wr[threadIdx.x], w1 = wr[threadIdx.x + 256];
    float4 y0 = make_float4(v0.x*rinv*w0.x, v0.y*rinv*w0.y, v0.z*rinv*w0.z, v0.w*rinv*w0.w);
    float4 y1 = make_float4(v1.x*rinv*w1.x, v1.y*rinv*w1.y, v1.z*rinv*w1.z, v1.w*rinv*w1.w);
    store_hilo4(y0, ohi, olo, base + threadIdx.x * 4);
    store_hilo4(y1, ohi, olo, base + (threadIdx.x + 256) * 4);
}

// ======================================================================
// bf16 split GEMM on mma.sync (m16n8k16): C = A@W^T (+bias)(+res), fp32.
// 128(M)x64(N) block tile, BK=64, 2-stage cp.async, 2 CTAs/SM.
// 8 warps in 2(M)x4(N); warp tile 64x16 = 4x2 m16n8 atoms; acc 32 f32.
// 3 split products (AhiWhi + AhiWlo + AloWhi) share fp32 accumulators.
// Stage layout: Ahi 16K | Alo 16K | Bhi 8K | Blo 8K  = 48KB
// ======================================================================
#define GSTAGE 49152
#define GSMEM  (2 * GSTAGE)               // 96 KB -> 2 CTAs/SM

__global__ __launch_bounds__(256, 2) void hgemm_kernel(
    const __nv_bfloat16* __restrict__ Ahi, const __nv_bfloat16* __restrict__ Alo,
    const __nv_bfloat16* __restrict__ Whi, const __nv_bfloat16* __restrict__ Wlo,
    const float* __restrict__ bias, const float* __restrict__ res,
    float* __restrict__ C, int M, int N, int K)
{
    extern __shared__ char smem[];
    uint32_t sb = smem_u32(smem);
    int tid = threadIdx.x, wid = tid >> 5, lt = tid & 31;
    int bm = blockIdx.y, bn = blockIdx.x;
    int wm = wid & 1, wn = wid >> 1;      // wm 0-1 (M), wn 0-3 (N)

    long aoff = (long)bm * 128 * K;
    long boff = (long)bn * 64 * K;
    const __nv_bfloat16* srcA[2] = {Ahi + aoff, Alo + aoff};
    const __nv_bfloat16* srcB[2] = {Whi + boff, Wlo + boff};

    // ---- global->smem fill coords (cp.async, 16B per chunk) ----
    int r0   = tid >> 3;                  // 0..31 base row, +32 per j
    int cb0  = (tid & 7) * 16;            // byte col in 128B row
    int gcol = (tid & 7) * 8;             // element col
    uint32_t sw_st = (uint32_t)(r0 & 7) << 4;
    uint32_t cbs   = (uint32_t)cb0 ^ sw_st;
    uint32_t st_off[4];
    #pragma unroll
    for (int j = 0; j < 4; j++)
        st_off[j] = (uint32_t)(r0 + j * 32) * 128 + cbs;

    // ---- ldmatrix address precompute ----
    int rA = wm * 64 + (lt & 15);
    uint32_t swA   = (uint32_t)(rA & 7) << 4;
    uint32_t baseA = (uint32_t)rA * 128;
    uint32_t cbA   = (uint32_t)((lt >> 4) << 4);       // 0 / 16

    int nB = wn * 16 + (lt & 7);
    uint32_t swB   = (uint32_t)(nB & 7) << 4;
    uint32_t baseB = (uint32_t)nB * 128;
    uint32_t cbB   = (uint32_t)(((lt >> 3) & 1) << 4); // 0 / 16

    float acc[4][2][4];
    #pragma unroll
    for (int mi = 0; mi < 4; mi++)
        #pragma unroll
        for (int ni = 0; ni < 2; ni++)
            #pragma unroll
            for (int q = 0; q < 4; q++) acc[mi][ni][q] = 0.f;

    int nit = K / 64;

    // stage fill helper (A: 4 row-groups of 32; B: 2 row-groups of 32)
    // prologue: stage 0
    {
        uint32_t sp = sb;
        #pragma unroll
        for (int tl = 0; tl < 2; tl++)
            #pragma unroll
            for (int j = 0; j < 4; j++)
                cp16(sp + tl * 16384 + st_off[j],
                     srcA[tl] + (long)(r0 + j * 32) * K + gcol);
        #pragma unroll
        for (int tl = 0; tl < 2; tl++)
            #pragma unroll
            for (int j = 0; j < 2; j++)
                cp16(sp + 32768 + tl * 8192 + st_off[j],
                     srcB[tl] + (long)(r0 + j * 32) * K + gcol);
        CP_COMMIT();
    }

    for (int it = 0; it < nit; it++) {
        int p = it & 1;
        CP_WAIT0();
        __syncthreads();

        if (it + 1 < nit) {
            int k0 = (it + 1) * 64;
            uint32_t sp = sb + (p ^ 1) * GSTAGE;
            #pragma unroll
            for (int tl = 0; tl < 2; tl++)
                #pragma unroll
                for (int j = 0; j < 4; j++)
                    cp16(sp + tl * 16384 + st_off[j],
                         srcA[tl] + (long)(r0 + j * 32) * K + k0 + gcol);
            #pragma unroll
            for (int tl = 0; tl < 2; tl++)
                #pragma unroll
                for (int j = 0; j < 2; j++)
                    cp16(sp + 32768 + tl * 8192 + st_off[j],
                         srcB[tl] + (long)(r0 + j * 32) * K + k0 + gcol);
            CP_COMMIT();
        }

        uint32_t tAhi = sb + p * GSTAGE;
        uint32_t tAlo = tAhi + 16384;
        uint32_t tWhi = tAhi + 32768;
        uint32_t tWlo = tAhi + 40960;

        #pragma unroll
        for (int ks = 0; ks < 4; ks++) {
            uint32_t ca  = ((uint32_t)(ks * 32) + cbA) ^ swA;
            uint32_t cbv = ((uint32_t)(ks * 32) + cbB) ^ swB;
            uint32_t a[4][4], bh[2][2], bl[2][2];

            #pragma unroll
            for (int mi = 0; mi < 4; mi++)
                ldm_x4(a[mi], tAhi + baseA + mi * 2048 + ca);
            #pragma unroll
            for (int ni = 0; ni < 2; ni++)
                ldm_x2(bh[ni], tWhi + baseB + ni * 1024 + cbv);
            #pragma unroll
            for (int mi = 0; mi < 4; mi++)
                #pragma unroll
                for (int ni = 0; ni < 2; ni++)
                    mma_bf16(acc[mi][ni], a[mi], bh[ni]);

            #pragma unroll
            for (int ni = 0; ni < 2; ni++)
                ldm_x2(bl[ni], tWlo + baseB + ni * 1024 + cbv);
            #pragma unroll
            for (int mi = 0; mi < 4; mi++)
                #pragma unroll
                for (int ni = 0; ni < 2; ni++)
                    mma_bf16(acc[mi][ni], a[mi], bl[ni]);

            #pragma unroll
            for (int mi = 0; mi < 4; mi++)
                ldm_x4(a[mi], tAlo + baseA + mi * 2048 + ca);
            #pragma unroll
            for (int mi = 0; mi < 4; mi++)
                #pragma unroll
                for (int ni = 0; ni < 2; ni++)
                    mma_bf16(acc[mi][ni], a[mi], bh[ni]);
        }
    }

    // ---- epilogue ----
    int row0 = bm * 128 + wm * 64 + (lt >> 2);
    int col0 = bn * 64 + wn * 16 + (lt & 3) * 2;
    #pragma unroll
    for (int mi = 0; mi < 4; mi++) {
        #pragma unroll
        for (int ni = 0; ni < 2; ni++) {
            long r = row0 + mi * 16;
            long c = col0 + ni * 8;
            float v0 = acc[mi][ni][0], v1 = acc[mi][ni][1];
            float v2 = acc[mi][ni][2], v3 = acc[mi][ni][3];
            if (bias) {
                float b0 = bias[c], b1 = bias[c + 1];
                v0 += b0; v1 += b1; v2 += b0; v3 += b1;
            }
            if (res) {
                const float2 r01 = *(const float2*)(res + r * N + c);
                const float2 r23 = *(const float2*)(res + (r + 8) * N + c);
                v0 += r01.x; v1 += r01.y; v2 += r23.x; v3 += r23.y;
            }
            *(float2*)(C + r * N + c)       = make_float2(v0, v1);
            *(float2*)(C + (r + 8) * N + c) = make_float2(v2, v3);
        }
    }
}

// ======================================================================
// Per-head RMSNorm + RoPE, in-place on g_q / g_k.
// ======================================================================
__global__ __launch_bounds__(128) void qknorm_rope_kernel(
    const float* __restrict__ cosb, const float* __restrict__ sinb,
    const float* __restrict__ qw, const float* __restrict__ kw)
{
    int t  = blockIdx.x;
    int hy = blockIdx.y;
    float* ptr; const float* w;
    if (hy < NH) { ptr = g_q + ((long)t * NH  + hy)        * DH; w = qw; }
    else         { ptr = g_k + ((long)t * NKV + (hy - NH)) * DH; w = kw; }

    int d = threadIdx.x;
    __shared__ float buf[DH];
    __shared__ float red[4];

    float v = ptr[d];
    buf[d] = v;
    float s = v * v;
    #pragma unroll
    for (int o = 16; o > 0; o >>= 1) s += __shfl_xor_sync(0xffffffff, s, o);
    if ((d & 31) == 0) red[d >> 5] = s;
    __syncthreads();
    float tot  = red[0] + red[1] + red[2] + red[3];
    float rinv = rsqrtf(tot / (float)DH + EPSV);

    int   p  = (d < 64) ? d + 64 : d - 64;
    float me = buf[d] * rinv * w[d];
    float pn = buf[p] * rinv * w[p];
    float rh = (d < 64) ? -pn : pn;
    float cv = cosb[(long)t * DH + d];
    float sv = sinb[(long)t * DH + d];
    ptr[d] = me * cv + rh * sv;
}

// ======================================================================
// Causal flash attention (fp32 online softmax). Output -> bf16 hi/lo.
// Warp-uniform inner loop; causality enforced per element via -inf.
// ======================================================================
#define QT 64
#define KT 32
__global__ __launch_bounds__(256) void attn_kernel()
{
    int bh = blockIdx.x;
    int qt = blockIdx.y;
    int b  = bh / NH, h = bh % NH;
    int kvh = h / (NH / NKV);

    int tid   = threadIdx.x;
    int qi    = tid >> 2;
    int lane4 = tid & 3;
    int base  = lane4 * 32;

    int  qrow = qt * QT + qi;
    long t    = (long)b * SEQ + qrow;

    const float* qp = g_q + (t * NH + h) * DH + base;
    float qreg[32], oreg[32];
    #pragma unroll
    for (int i = 0; i < 32; i++) { qreg[i] = qp[i]; oreg[i] = 0.f; }

    float m = -INFINITY, l = 0.f;
    const float scale = 0.08838834764831845f;

    __shared__ float Ks[KT][DH];
    __shared__ float Vs[KT][DH];

    int nkt = (qt * QT + QT) / KT;
    for (int kt = 0; kt < nkt; kt++) {
        __syncthreads();
        for (int idx = tid; idx < KT * DH / 4; idx += 256) {
            int kr = (idx * 4) / DH;
            int kc = (idx * 4) % DH;
            long ktok = (long)b * SEQ + kt * KT + kr;
            *(float4*)&Ks[kr][kc] = *(const float4*)(g_k + (ktok * NKV + kvh) * DH + kc);
            *(float4*)&Vs[kr][kc] = *(const float4*)(g_v + (ktok * NKV + kvh) * DH + kc);
        }
        __syncthreads();

        #pragma unroll 4
        for (int j = 0; j < KT; j++) {
            const float4* kr4 = (const float4*)&Ks[j][base];
            float d0 = 0.f, d1 = 0.f, d2 = 0.f, d3 = 0.f;
            #pragma unroll
            for (int i4 = 0; i4 < 8; i4++) {
                float4 kv = kr4[i4];
                d0 += qreg[i4 * 4 + 0] * kv.x;
                d1 += qreg[i4 * 4 + 1] * kv.y;
                d2 += qreg[i4 * 4 + 2] * kv.z;
                d3 += qreg[i4 * 4 + 3] * kv.w;
            }
            float dot = (d0 + d1) + (d2 + d3);
            dot += __shfl_xor_sync(0xffffffff, dot, 1);
            dot += __shfl_xor_sync(0xffffffff, dot, 2);

            float sc = (kt * KT + j <= qrow) ? dot * scale : -INFINITY;

            float mn   = fmaxf(m, sc);
            float corr = __expf(m - mn);
            float p    = __expf(sc - mn);
            l = l * corr + p;
            m = mn;

            const float4* vr4 = (const float4*)&Vs[j][base];
            #pragma unroll
            for (int i4 = 0; i4 < 8; i4++) {
                float4 vv = vr4[i4];
                oreg[i4 * 4 + 0] = oreg[i4 * 4 + 0] * corr + p * vv.x;
                oreg[i4 * 4 + 1] = oreg[i4 * 4 + 1] * corr + p * vv.y;
                oreg[i4 * 4 + 2] = oreg[i4 * 4 + 2] * corr + p * vv.z;
                oreg[i4 * 4 + 3] = oreg[i4 * 4 + 3] * corr + p * vv.w;
            }
        }
    }

    float inv = 1.f / l;
    long obase = (t * NH + h) * DH + base;
    #pragma unroll
    for (int q = 0; q < 8; q++) {
        float4 v = make_float4(oreg[q*4+0]*inv, oreg[q*4+1]*inv,
                               oreg[q*4+2]*inv, oreg[q*4+3]*inv);
        store_hilo4(v, g_attn_hi, g_attn_lo, obase + q * 4);
    }
}

// ======================================================================
// act = silu(gate) * up -> bf16 hi/lo
// ======================================================================
__global__ __launch_bounds__(256) void silu_mul_kernel()
{
    long i4 = ((long)blockIdx.x * 256 + threadIdx.x) * 4;
    float4 g = *(float4*)&g_gate[i4];
    float4 u = *(float4*)&g_up[i4];
    g.x = (g.x / (1.f + __expf(-g.x))) * u.x;
    g.y = (g.y / (1.f + __expf(-g.y))) * u.y;
    g.z = (g.z / (1.f + __expf(-g.z))) * u.z;
    g.w = (g.w / (1.f + __expf(-g.w))) * u.w;
    store_hilo4(g, g_act_hi, g_act_lo, i4);
}

// ======================================================================
// launch
// ======================================================================
extern "C" void kernel_launch(void* const* d_in, const int* in_sizes, int n_in,
                              void* d_out, int out_size)
{
    const float* x    = (const float*)d_in[0];
    const float* cosb = (const float*)d_in[2];
    const float* sinb = (const float*)d_in[3];
    const float* wq   = (const float*)d_in[4];
    const float* bq   = (const float*)d_in[5];
    const float* wk   = (const float*)d_in[6];
    const float* bk   = (const float*)d_in[7];
    const float* wv   = (const float*)d_in[8];
    const float* bv   = (const float*)d_in[9];
    const float* wo   = (const float*)d_in[10];
    const float* qnw  = (const float*)d_in[11];
    const float* knw  = (const float*)d_in[12];
    const float* ln1  = (const float*)d_in[13];
    const float* ln2  = (const float*)d_in[14];
    const float* wg   = (const float*)d_in[15];
    const float* wu   = (const float*)d_in[16];
    const float* wd   = (const float*)d_in[17];
    float* out = (float*)d_out;

    float *pq, *pk, *pv, *pgate, *pup;
    __nv_bfloat16 *phh, *phl, *pah, *pal, *pch, *pcl;
    __nv_bfloat16 *qh, *ql, *kh, *kl, *vh, *vl, *oh, *ol, *gh, *gl, *uh, *ul, *dh, *dl;
    cudaGetSymbolAddress((void**)&pq,    g_q);
    cudaGetSymbolAddress((void**)&pk,    g_k);
    cudaGetSymbolAddress((void**)&pv,    g_v);
    cudaGetSymbolAddress((void**)&pgate, g_gate);
    cudaGetSymbolAddress((void**)&pup,   g_up);
    cudaGetSymbolAddress((void**)&phh, g_h_hi);   cudaGetSymbolAddress((void**)&phl, g_h_lo);
    cudaGetSymbolAddress((void**)&pah, g_attn_hi);cudaGetSymbolAddress((void**)&pal, g_attn_lo);
    cudaGetSymbolAddress((void**)&pch, g_act_hi); cudaGetSymbolAddress((void**)&pcl, g_act_lo);
    cudaGetSymbolAddress((void**)&qh, w_q_hi);    cudaGetSymbolAddress((void**)&ql, w_q_lo);
    cudaGetSymbolAddress((void**)&kh, w_k_hi);    cudaGetSymbolAddress((void**)&kl, w_k_lo);
    cudaGetSymbolAddress((void**)&vh, w_v_hi);    cudaGetSymbolAddress((void**)&vl, w_v_lo);
    cudaGetSymbolAddress((void**)&oh, w_o_hi);    cudaGetSymbolAddress((void**)&ol, w_o_lo);
    cudaGetSymbolAddress((void**)&gh, w_g_hi);    cudaGetSymbolAddress((void**)&gl, w_g_lo);
    cudaGetSymbolAddress((void**)&uh, w_u_hi);    cudaGetSymbolAddress((void**)&ul, w_u_lo);
    cudaGetSymbolAddress((void**)&dh, w_d_hi);    cudaGetSymbolAddress((void**)&dl, w_d_lo);

    // not a stream op; safe under capture, deterministic every call
    cudaFuncSetAttribute(hgemm_kernel, cudaFuncAttributeMaxDynamicSharedMemorySize, GSMEM);

    // weight fp32 -> bf16 hi/lo
    auto conv = [&](const float* s, __nv_bfloat16* h, __nv_bfloat16* l, long n) {
        convert_hilo_kernel<<<(unsigned)((n / 4 + 255) / 256), 256>>>(s, h, l, (int)(n / 4));
    };
    conv(wq, qh, ql, (long)NH  * DH * HID);
    conv(wk, kh, kl, (long)NKV * DH * HID);
    conv(wv, vh, vl, (long)NKV * DH * HID);
    conv(wo, oh, ol, (long)HID * NH * DH);
    conv(wg, gh, gl, (long)INTER * HID);
    conv(wu, uh, ul, (long)INTER * HID);
    conv(wd, dh, dl, (long)HID * INTER);

    // 1. h = rms(x, ln1) -> bf16 hi/lo
    rmsnorm_kernel<<<T_TOK, 256>>>(x, ln1, phh, phl);

    // 2-4. q/k/v projections (tensor cores via mma.sync)
    hgemm_kernel<<<dim3((NH * DH) / 64, T_TOK / 128), 256, GSMEM>>>(
        phh, phl, qh, ql, bq, nullptr, pq, T_TOK, NH * DH, HID);
    hgemm_kernel<<<dim3((NKV * DH) / 64, T_TOK / 128), 256, GSMEM>>>(
        phh, phl, kh, kl, bk, nullptr, pk, T_TOK, NKV * DH, HID);
    hgemm_kernel<<<dim3((NKV * DH) / 64, T_TOK / 128), 256, GSMEM>>>(
        phh, phl, vh, vl, bv, nullptr, pv, T_TOK, NKV * DH, HID);

    // 5. per-head rmsnorm + rope
    qknorm_rope_kernel<<<dim3(T_TOK, NH + NKV), 128>>>(cosb, sinb, qnw, knw);

    // 6. attention -> bf16 hi/lo
    attn_kernel<<<dim3(BATCH * NH, SEQ / QT), 256>>>();

    // 7. x1 = x + attn @ wo^T  (into d_out)
    hgemm_kernel<<<dim3(HID / 64, T_TOK / 128), 256, GSMEM>>>(
        pah, pal, oh, ol, nullptr, x, out, T_TOK, HID, NH * DH);

    // 8. h2 = rms(x1, ln2) -> bf16 hi/lo
    rmsnorm_kernel<<<T_TOK, 256>>>(out, ln2, phh, phl);

    // 9-10. gate / up projections
    hgemm_kernel<<<dim3(INTER / 64, T_TOK / 128), 256, GSMEM>>>(
        phh, phl, gh, gl, nullptr, nullptr, pgate, T_TOK, INTER, HID);
    hgemm_kernel<<<dim3(INTER / 64, T_TOK / 128), 256, GSMEM>>>(
        phh, phl, uh, ul, nullptr, nullptr, pup, T_TOK, INTER, HID);

    // 11. act = silu(gate) * up -> bf16 hi/lo
    silu_mul_kernel<<<(T_TOK * (long)INTER) / (256 * 4), 256>>>();

    // 12. out = x1 + act @ wd^T
    hgemm_kernel<<<dim3(HID / 64, T_TOK / 128), 256, GSMEM>>>(
        pch, pcl, dh, dl, nullptr, out, out, T_TOK, HID, INTER);
}